// round 1
// baseline (speedup 1.0000x reference)
#include <cuda_runtime.h>
#include <cuda_bf16.h>
#include <math.h>
#include <float.h>

// ---------------------------------------------------------------------------
// Problem constants (fixed by the dataset)
// ---------------------------------------------------------------------------
#define NTOK   4096          // 2*2048 tokens
#define DMODEL 1024
#define DFF    4096
#define DN     128
#define NHEADS 8
#define HDIM   16
#define TOPK   32

// ---------------------------------------------------------------------------
// Scratch (no cudaMalloc allowed -> __device__ globals)
// ---------------------------------------------------------------------------
__device__ float g_xn[NTOK * DMODEL];            // 16 MB
__device__ float g_h[NTOK * DMODEL];             // 16 MB
__device__ float g_scores[(size_t)NTOK * DFF];   // 64 MB
__device__ int   g_idx[NTOK * TOPK];
__device__ float g_qkv[(size_t)NTOK * TOPK * 3 * DN]; // 192 MB

// ---------------------------------------------------------------------------
// Helpers
// ---------------------------------------------------------------------------
__device__ __forceinline__ float gelu_f(float v) {
    return 0.5f * v * (1.0f + erff(v * 0.70710678118654752f));
}
__device__ __forceinline__ float warp_sum(float v) {
    #pragma unroll
    for (int o = 16; o > 0; o >>= 1) v += __shfl_xor_sync(0xffffffffu, v, o);
    return v;
}
__device__ __forceinline__ float warp_max(float v) {
    #pragma unroll
    for (int o = 16; o > 0; o >>= 1) v = fmaxf(v, __shfl_xor_sync(0xffffffffu, v, o));
    return v;
}

// ---------------------------------------------------------------------------
// LayerNorm: one block per token row
// ---------------------------------------------------------------------------
__global__ void ln_kernel(const float* __restrict__ x,
                          const float* __restrict__ g,
                          const float* __restrict__ b,
                          float* __restrict__ xn) {
    __shared__ float red[16];
    __shared__ float s_mu, s_r;
    int n = blockIdx.x, tid = threadIdx.x, w = tid >> 5, lane = tid & 31;
    float4 v = ((const float4*)(x + (size_t)n * DMODEL))[tid];
    float s = v.x + v.y + v.z + v.w;
    float q = v.x * v.x + v.y * v.y + v.z * v.z + v.w * v.w;
    s = warp_sum(s); q = warp_sum(q);
    if (lane == 0) { red[w] = s; red[8 + w] = q; }
    __syncthreads();
    if (tid == 0) {
        float ts = 0.f, tq = 0.f;
        for (int i = 0; i < 8; i++) { ts += red[i]; tq += red[8 + i]; }
        float mu = ts * (1.0f / DMODEL);
        float var = tq * (1.0f / DMODEL) - mu * mu;
        s_mu = mu; s_r = rsqrtf(var + 1e-5f);
    }
    __syncthreads();
    float mu = s_mu, r = s_r;
    float4 gv = ((const float4*)g)[tid];
    float4 bv = ((const float4*)b)[tid];
    float4 o;
    o.x = (v.x - mu) * r * gv.x + bv.x;
    o.y = (v.y - mu) * r * gv.y + bv.y;
    o.z = (v.z - mu) * r * gv.z + bv.z;
    o.w = (v.w - mu) * r * gv.w + bv.w;
    ((float4*)(xn + (size_t)n * DMODEL))[tid] = o;
}

// ---------------------------------------------------------------------------
// Tiled SGEMM: C[M,N] = act(A[M,K] @ B[N,K]^T + bias)
//   A row-major (row optionally gathered via rowidx), B row-major [N,K].
//   BM=BN=64, BK=16, 256 threads, 4x4 per-thread microtile.
// ---------------------------------------------------------------------------
template <int ACT>
__global__ void sgemm_kernel(const float* __restrict__ A,
                             const float* __restrict__ B,
                             const float* __restrict__ bias,
                             const int* __restrict__ rowidx,
                             float* __restrict__ C,
                             int M, int N, int K) {
    __shared__ float As[16 * 68];
    __shared__ float Bs[16 * 68];
    int tid = threadIdx.x;
    int tx = tid & 15, ty = tid >> 4;
    int m0 = blockIdx.y * 64, n0 = blockIdx.x * 64;
    int lrow = tid >> 2, c4 = tid & 3;

    int arow = m0 + lrow;
    if (rowidx) arow = rowidx[arow];
    const float4* A4 = (const float4*)(A + (size_t)arow * K);
    const float4* B4 = (const float4*)(B + (size_t)(n0 + lrow) * K);

    float acc[4][4];
    #pragma unroll
    for (int i = 0; i < 4; i++)
        #pragma unroll
        for (int j = 0; j < 4; j++) acc[i][j] = 0.f;

    int KT = K >> 4;
    for (int kt = 0; kt < KT; kt++) {
        float4 av = A4[kt * 4 + c4];
        float4 bv = B4[kt * 4 + c4];
        __syncthreads();
        int kb = c4 * 4;
        As[(kb + 0) * 68 + lrow] = av.x;
        As[(kb + 1) * 68 + lrow] = av.y;
        As[(kb + 2) * 68 + lrow] = av.z;
        As[(kb + 3) * 68 + lrow] = av.w;
        Bs[(kb + 0) * 68 + lrow] = bv.x;
        Bs[(kb + 1) * 68 + lrow] = bv.y;
        Bs[(kb + 2) * 68 + lrow] = bv.z;
        Bs[(kb + 3) * 68 + lrow] = bv.w;
        __syncthreads();
        #pragma unroll
        for (int kk = 0; kk < 16; kk++) {
            float4 a = *(const float4*)&As[kk * 68 + ty * 4];
            float4 bq = *(const float4*)&Bs[kk * 68 + tx * 4];
            float aa[4] = {a.x, a.y, a.z, a.w};
            float bb[4] = {bq.x, bq.y, bq.z, bq.w};
            #pragma unroll
            for (int i = 0; i < 4; i++)
                #pragma unroll
                for (int j = 0; j < 4; j++)
                    acc[i][j] = fmaf(aa[i], bb[j], acc[i][j]);
        }
    }
    #pragma unroll
    for (int i = 0; i < 4; i++) {
        #pragma unroll
        for (int j = 0; j < 4; j++) {
            float v = acc[i][j];
            if (bias) v += bias[n0 + tx * 4 + j];
            if (ACT == 1) v = gelu_f(v);
            C[(size_t)(m0 + ty * 4 + i) * N + n0 + tx * 4 + j] = v;
        }
    }
}

// ---------------------------------------------------------------------------
// Top-32 per row of scores[NTOK, DFF] — iterative argmax in shared memory.
// ---------------------------------------------------------------------------
__global__ void topk_kernel(const float* __restrict__ scores,
                            int* __restrict__ idxout) {
    __shared__ float sv[DFF];
    __shared__ float swv[8];
    __shared__ int   swi[8];
    int n = blockIdx.x, tid = threadIdx.x, w = tid >> 5, lane = tid & 31;
    const float4* s4 = (const float4*)(scores + (size_t)n * DFF);
    for (int i = tid; i < DFF / 4; i += 256)
        ((float4*)sv)[i] = s4[i];
    __syncthreads();
    for (int r = 0; r < TOPK; r++) {
        float best = -FLT_MAX;
        int bi = 0;
        for (int j = tid; j < DFF; j += 256) {
            float v = sv[j];
            if (v > best) { best = v; bi = j; }
        }
        #pragma unroll
        for (int o = 16; o > 0; o >>= 1) {
            float ov = __shfl_down_sync(0xffffffffu, best, o);
            int   oi = __shfl_down_sync(0xffffffffu, bi, o);
            if (ov > best || (ov == best && oi < bi)) { best = ov; bi = oi; }
        }
        if (lane == 0) { swv[w] = best; swi[w] = bi; }
        __syncthreads();
        if (tid == 0) {
            float b = swv[0]; int bx = swi[0];
            for (int q = 1; q < 8; q++)
                if (swv[q] > b || (swv[q] == b && swi[q] < bx)) { b = swv[q]; bx = swi[q]; }
            idxout[n * TOPK + r] = bx;
            sv[bx] = -FLT_MAX;
        }
        __syncthreads();
    }
}

// ---------------------------------------------------------------------------
// Fused per-token kernel: base gate, 8-head attention over k=32 neurons,
// out_proj, gating MLP, and weighted sum of output directions.
// One block per token, 256 threads, ~111 KB dynamic smem.
// ---------------------------------------------------------------------------
#define SQKV_STRIDE 388      // 384 + 4 pad (4-way banks instead of 32-way)
#define WT_STRIDE   132      // 128 + 4 pad, float4-aligned
#define TOKEN_SMEM_FLOATS (16896 + 1024 + 4096 + 4096 + 2112 + 32 + 32 + 32)

__global__ void token_kernel(const float* __restrict__ x,
                             const float* __restrict__ pats,
                             const float* __restrict__ dirs,
                             const float* __restrict__ outw,
                             const float* __restrict__ outb,
                             const float* __restrict__ wp1,
                             const float* __restrict__ wp1b,
                             const float* __restrict__ wp2,
                             const float* __restrict__ wp2b,
                             const int* __restrict__ idx,
                             const float* __restrict__ qkv,
                             float* __restrict__ out) {
    extern __shared__ float sm[];
    float* sW    = sm;              // 16896 floats: qkv+att, then wT, then wp1T
    float* sx    = sm + 16896;      // 1024
    float* sao   = sx + 1024;       // 4096
    float* satd  = sao + 4096;      // 4096
    float* sg1   = satd + 4096;     // 2112 = 64*33
    float* sbase = sg1 + 2112;      // 32
    float* sgate = sbase + 32;      // 32
    int*   skid  = (int*)(sgate + 32); // 32
    float* sqkv  = sW;              // 32 rows, stride 388 -> 12416 floats
    float* satt  = sW + 12416;      // 1024

    int n = blockIdx.x, tid = threadIdx.x, w = tid >> 5, lane = tid & 31;

    if (tid < TOPK) skid[tid] = idx[n * TOPK + tid];
    ((float4*)sx)[tid] = ((const float4*)x)[(size_t)n * 256 + tid];
    __syncthreads();

    // qkv -> smem (padded rows)
    {
        const float* qn = qkv + (size_t)n * (TOPK * 3 * DN);
        for (int i = tid; i < TOPK * 3 * DN; i += 256) {
            int r = i / 384, c = i - r * 384;
            sqkv[r * SQKV_STRIDE + c] = qn[i];
        }
    }

    // base[k] = gelu(x . pats[idx_k])  — one warp handles 4 k's
    {
        const float4* xs = (const float4*)sx;
        #pragma unroll
        for (int r = 0; r < 4; r++) {
            int kk = w * 4 + r;
            const float4* p = (const float4*)(pats + (size_t)skid[kk] * DMODEL);
            float s = 0.f;
            #pragma unroll
            for (int j = 0; j < 8; j++) {
                int i = lane + 32 * j;
                float4 a = p[i], b = xs[i];
                s += a.x * b.x + a.y * b.y + a.z * b.z + a.w * b.w;
            }
            s = warp_sum(s);
            if (lane == 0) sbase[kk] = gelu_f(s);
        }
    }
    __syncthreads();

    // attention, head by head
    for (int h = 0; h < NHEADS; h++) {
        #pragma unroll
        for (int it = 0; it < 4; it++) {
            int e = tid + 256 * it;
            int qi = e >> 5, ki = e & 31;
            const float4* q4 = (const float4*)(sqkv + qi * SQKV_STRIDE + h * HDIM);
            const float4* k4 = (const float4*)(sqkv + ki * SQKV_STRIDE + DN + h * HDIM);
            float s = 0.f;
            #pragma unroll
            for (int j = 0; j < 4; j++) {
                float4 a = q4[j], b = k4[j];
                s += a.x * b.x + a.y * b.y + a.z * b.z + a.w * b.w;
            }
            satt[e] = s * 0.25f;
        }
        __syncthreads();
        #pragma unroll
        for (int r = 0; r < 4; r++) {
            int qi = w * 4 + r;
            float v = satt[qi * 32 + lane];
            float m = warp_max(v);
            float e2 = __expf(v - m);
            float s = warp_sum(e2);
            satt[qi * 32 + lane] = e2 / s;
        }
        __syncthreads();
        #pragma unroll
        for (int it = 0; it < 2; it++) {
            int e = tid + 256 * it;
            int qi = e >> 4, dc = e & 15;
            float s = 0.f;
            #pragma unroll
            for (int ki = 0; ki < 32; ki++)
                s = fmaf(satt[qi * 32 + ki], sqkv[ki * SQKV_STRIDE + 2 * DN + h * HDIM + dc], s);
            sao[qi * DN + h * HDIM + dc] = s;
        }
        __syncthreads();
    }

    // attended = ao @ out_proj_w^T + b : stage w transposed in smem
    for (int i = tid; i < DN * DN; i += 256) {
        int o = i >> 7, d = i & 127;
        sW[d * WT_STRIDE + o] = outw[i];
    }
    __syncthreads();
    {
        int rb = w, cb = lane;   // rows rb*4.., cols cb*4..
        float acc[4][4];
        #pragma unroll
        for (int i = 0; i < 4; i++)
            #pragma unroll
            for (int j = 0; j < 4; j++) acc[i][j] = 0.f;
        for (int d = 0; d < DN; d++) {
            float4 wv = *(const float4*)&sW[d * WT_STRIDE + cb * 4];
            float wa[4] = {wv.x, wv.y, wv.z, wv.w};
            #pragma unroll
            for (int i = 0; i < 4; i++) {
                float a = sao[(rb * 4 + i) * DN + d];
                #pragma unroll
                for (int j = 0; j < 4; j++) acc[i][j] = fmaf(a, wa[j], acc[i][j]);
            }
        }
        #pragma unroll
        for (int i = 0; i < 4; i++)
            #pragma unroll
            for (int j = 0; j < 4; j++)
                satd[(rb * 4 + i) * DN + cb * 4 + j] = acc[i][j] + outb[cb * 4 + j];
    }
    __syncthreads();

    // g1 = gelu(attended @ wp1^T + b1)
    for (int i = tid; i < 64 * DN; i += 256) {
        int o = i >> 7, d = i & 127;
        sW[d * WT_STRIDE + o] = wp1[i];
    }
    __syncthreads();
    {
        int rb = tid >> 4, cb = tid & 15;   // rows rb*2.., cols cb*4..
        float acc[2][4];
        #pragma unroll
        for (int i = 0; i < 2; i++)
            #pragma unroll
            for (int j = 0; j < 4; j++) acc[i][j] = 0.f;
        for (int d = 0; d < DN; d++) {
            float4 wv = *(const float4*)&sW[d * WT_STRIDE + cb * 4];
            float wa[4] = {wv.x, wv.y, wv.z, wv.w};
            #pragma unroll
            for (int i = 0; i < 2; i++) {
                float a = satd[(rb * 2 + i) * DN + d];
                #pragma unroll
                for (int j = 0; j < 4; j++) acc[i][j] = fmaf(a, wa[j], acc[i][j]);
            }
        }
        #pragma unroll
        for (int i = 0; i < 2; i++)
            #pragma unroll
            for (int j = 0; j < 4; j++)
                sg1[(cb * 4 + j) * 33 + rb * 2 + i] = gelu_f(acc[i][j] + wp1b[cb * 4 + j]);
    }
    __syncthreads();

    // g2 = sigmoid(g1 @ wp2^T + b2); final gate
    if (tid < TOPK) {
        float s = 0.f;
        #pragma unroll
        for (int j = 0; j < 64; j++) s = fmaf(sg1[j * 33 + tid], wp2[j], s);
        float sig = 1.0f / (1.0f + __expf(-(s + wp2b[0])));
        sgate[tid] = sbase[tid] * sig;
    }
    __syncthreads();

    // out[n,:] = sum_k gate[k] * dirs[idx_k,:]
    {
        float4 acc; acc.x = acc.y = acc.z = acc.w = 0.f;
        #pragma unroll 4
        for (int k = 0; k < TOPK; k++) {
            float g = sgate[k];
            const float4* dr = (const float4*)(dirs + (size_t)skid[k] * DMODEL);
            float4 v = dr[tid];
            acc.x = fmaf(g, v.x, acc.x);
            acc.y = fmaf(g, v.y, acc.y);
            acc.z = fmaf(g, v.z, acc.z);
            acc.w = fmaf(g, v.w, acc.w);
        }
        ((float4*)out)[(size_t)n * 256 + tid] = acc;
    }
}

// ---------------------------------------------------------------------------
// Launch
// ---------------------------------------------------------------------------
extern "C" void kernel_launch(void* const* d_in, const int* in_sizes, int n_in,
                              void* d_out, int out_size) {
    const float* x    = (const float*)d_in[0];
    const float* pats = (const float*)d_in[1];
    const float* vecs = (const float*)d_in[2];
    const float* dirs = (const float*)d_in[3];
    const float* rw1  = (const float*)d_in[4];
    const float* rw2  = (const float*)d_in[5];
    const float* lng  = (const float*)d_in[6];
    const float* lnb  = (const float*)d_in[7];
    const float* inw  = (const float*)d_in[8];
    const float* inb  = (const float*)d_in[9];
    const float* outw = (const float*)d_in[10];
    const float* outb = (const float*)d_in[11];
    const float* wp1  = (const float*)d_in[12];
    const float* wp1b = (const float*)d_in[13];
    const float* wp2  = (const float*)d_in[14];
    const float* wp2b = (const float*)d_in[15];
    float* out = (float*)d_out;

    float *p_xn, *p_h, *p_scores, *p_qkv;
    int *p_idx;
    cudaGetSymbolAddress((void**)&p_xn, g_xn);
    cudaGetSymbolAddress((void**)&p_h, g_h);
    cudaGetSymbolAddress((void**)&p_scores, g_scores);
    cudaGetSymbolAddress((void**)&p_idx, g_idx);
    cudaGetSymbolAddress((void**)&p_qkv, g_qkv);

    static int smem_set = 0;
    if (!smem_set) {
        cudaFuncSetAttribute(token_kernel,
                             cudaFuncAttributeMaxDynamicSharedMemorySize,
                             TOKEN_SMEM_FLOATS * 4);
        smem_set = 1;
    }

    // 1) LayerNorm
    ln_kernel<<<NTOK, 256>>>(x, lng, lnb, p_xn);

    // 2) h = gelu(xn @ rw1^T)
    sgemm_kernel<1><<<dim3(DMODEL / 64, NTOK / 64), 256>>>(
        p_xn, rw1, nullptr, nullptr, p_h, NTOK, DMODEL, DMODEL);

    // 3) scores = h @ rw2^T
    sgemm_kernel<0><<<dim3(DFF / 64, NTOK / 64), 256>>>(
        p_h, rw2, nullptr, nullptr, p_scores, NTOK, DFF, DMODEL);

    // 4) top-32 per token
    topk_kernel<<<NTOK, 256>>>(p_scores, p_idx);

    // 5) qkv = gather(neuron_vecs, idx) @ in_proj_w^T + b   (batched rows)
    sgemm_kernel<0><<<dim3((3 * DN) / 64, (NTOK * TOPK) / 64), 256>>>(
        vecs, inw, inb, p_idx, p_qkv, NTOK * TOPK, 3 * DN, DN);

    // 6) fused per-token attention + gating + output
    token_kernel<<<NTOK, 256, TOKEN_SMEM_FLOATS * 4>>>(
        x, pats, dirs, outw, outb, wp1, wp1b, wp2, wp2b, p_idx, p_qkv, out);
}

// round 4
// speedup vs baseline: 1.4509x; 1.4509x over previous
#include <cuda_runtime.h>
#include <cuda_bf16.h>
#include <math.h>
#include <float.h>
#include <stdint.h>

// ---------------------------------------------------------------------------
// Problem constants
// ---------------------------------------------------------------------------
#define NTOK   4096
#define DMODEL 1024
#define DFF    4096
#define DN     128
#define NHEADS 8
#define HDIM   16
#define TOPK   32

// ---------------------------------------------------------------------------
// Scratch
// ---------------------------------------------------------------------------
__device__ float g_xn[NTOK * DMODEL];
__device__ float g_h[NTOK * DMODEL];
__device__ float g_scores[(size_t)NTOK * DFF];
__device__ int   g_idx[NTOK * TOPK];
__device__ float g_qkv[(size_t)NTOK * TOPK * 3 * DN];

// ---------------------------------------------------------------------------
// Helpers
// ---------------------------------------------------------------------------
__device__ __forceinline__ float gelu_f(float v) {
    return 0.5f * v * (1.0f + erff(v * 0.70710678118654752f));
}
__device__ __forceinline__ float warp_sum(float v) {
    #pragma unroll
    for (int o = 16; o > 0; o >>= 1) v += __shfl_xor_sync(0xffffffffu, v, o);
    return v;
}
__device__ __forceinline__ float warp_max(float v) {
    #pragma unroll
    for (int o = 16; o > 0; o >>= 1) v = fmaxf(v, __shfl_xor_sync(0xffffffffu, v, o));
    return v;
}
__device__ __forceinline__ float tf32_rna(float x) {
    float r;
    asm("cvt.rna.tf32.f32 %0, %1;" : "=f"(r) : "f"(x));
    return r;
}

// m16n8k8 tf32 mma (sm_80+ feature -> compiles on plain sm_103 target)
__device__ __forceinline__ void mma8(float* c, const uint32_t a[4], const uint32_t b[2]) {
    asm volatile(
        "mma.sync.aligned.m16n8k8.row.col.f32.tf32.tf32.f32 "
        "{%0,%1,%2,%3}, {%4,%5,%6,%7}, {%8,%9}, {%0,%1,%2,%3};"
        : "+f"(c[0]), "+f"(c[1]), "+f"(c[2]), "+f"(c[3])
        : "r"(a[0]), "r"(a[1]), "r"(a[2]), "r"(a[3]), "r"(b[0]), "r"(b[1]));
}

#define GS 36   // smem row stride in floats (32 data + 4 pad)

__device__ __forceinline__ void frag_a(uint32_t a[4], const float* S, int row, int kc, int lane) {
    int r = lane >> 2, c = lane & 3;
    a[0] = __float_as_uint(S[(row + r) * GS + kc + c]);
    a[1] = __float_as_uint(S[(row + r + 8) * GS + kc + c]);
    a[2] = __float_as_uint(S[(row + r) * GS + kc + c + 4]);
    a[3] = __float_as_uint(S[(row + r + 8) * GS + kc + c + 4]);
}
__device__ __forceinline__ void frag_b(uint32_t b[2], const float* S, int col, int kc, int lane) {
    int n = lane >> 2, c = lane & 3;
    b[0] = __float_as_uint(S[(col + n) * GS + kc + c]);
    b[1] = __float_as_uint(S[(col + n) * GS + kc + c + 4]);
}

// ---------------------------------------------------------------------------
// LayerNorm
// ---------------------------------------------------------------------------
__global__ void ln_kernel(const float* __restrict__ x,
                          const float* __restrict__ g,
                          const float* __restrict__ b,
                          float* __restrict__ xn) {
    __shared__ float red[16];
    __shared__ float s_mu, s_r;
    int n = blockIdx.x, tid = threadIdx.x, w = tid >> 5, lane = tid & 31;
    float4 v = ((const float4*)(x + (size_t)n * DMODEL))[tid];
    float s = v.x + v.y + v.z + v.w;
    float q = v.x * v.x + v.y * v.y + v.z * v.z + v.w * v.w;
    s = warp_sum(s); q = warp_sum(q);
    if (lane == 0) { red[w] = s; red[8 + w] = q; }
    __syncthreads();
    if (tid == 0) {
        float ts = 0.f, tq = 0.f;
        for (int i = 0; i < 8; i++) { ts += red[i]; tq += red[8 + i]; }
        float mu = ts * (1.0f / DMODEL);
        float var = tq * (1.0f / DMODEL) - mu * mu;
        s_mu = mu; s_r = rsqrtf(var + 1e-5f);
    }
    __syncthreads();
    float mu = s_mu, r = s_r;
    float4 gv = ((const float4*)g)[tid];
    float4 bv = ((const float4*)b)[tid];
    float4 o;
    o.x = (v.x - mu) * r * gv.x + bv.x;
    o.y = (v.y - mu) * r * gv.y + bv.y;
    o.z = (v.z - mu) * r * gv.z + bv.z;
    o.w = (v.w - mu) * r * gv.w + bv.w;
    ((float4*)(xn + (size_t)n * DMODEL))[tid] = o;
}

// ---------------------------------------------------------------------------
// Tensor-core TF32 GEMM: C[M,N] = act(A[M,K] @ B[N,K]^T + bias)
// CTA tile 128x128, 8 warps of 64x32, K-chunks of 32, register prefetch.
// PASSES==3: 3xTF32 error compensation (hh + h*lo + lo*h).
// ---------------------------------------------------------------------------
template <int ACT, int PASSES>
__global__ void __launch_bounds__(256, 1)
mma_gemm(const float* __restrict__ A,
         const float* __restrict__ B,
         const float* __restrict__ bias,
         const int* __restrict__ rowidx,
         float* __restrict__ C,
         int K, int ldc, int kchunks) {
    extern __shared__ float sm[];
    float* Ah = sm;
    float* Al = Ah + 128 * GS;                        // PASSES==3 only
    float* Bh = Ah + (PASSES == 3 ? 2 : 1) * 128 * GS;
    float* Bl = Bh + 128 * GS;                        // PASSES==3 only

    int tid = threadIdx.x, lane = tid & 31, wid = tid >> 5;
    int m0 = blockIdx.y * 128, n0 = blockIdx.x * 128;
    int mw = (wid >> 2) * 64, nw = (wid & 3) * 32;

    // global load assignment: 4 rows per thread, 1 float4 each
    int r0 = tid >> 3, c4 = tid & 7;
    const float* Ap[4];
    const float* Bp[4];
    #pragma unroll
    for (int i = 0; i < 4; i++) {
        int r = r0 + 32 * i;
        int ar = rowidx ? rowidx[m0 + r] : (m0 + r);
        Ap[i] = A + (size_t)ar * K + c4 * 4;
        Bp[i] = B + (size_t)(n0 + r) * K + c4 * 4;
    }

    float acc[4][4][4];
    #pragma unroll
    for (int mt = 0; mt < 4; mt++)
        #pragma unroll
        for (int nt = 0; nt < 4; nt++)
            #pragma unroll
            for (int e = 0; e < 4; e++) acc[mt][nt][e] = 0.f;

    float4 pa[4], pb[4];
    #pragma unroll
    for (int i = 0; i < 4; i++) { pa[i] = *(const float4*)Ap[i]; pb[i] = *(const float4*)Bp[i]; }

    for (int ch = 0; ch < kchunks; ch++) {
        // stage current chunk into smem (with tf32 hi/lo split)
        #pragma unroll
        for (int i = 0; i < 4; i++) {
            int r = r0 + 32 * i;
            float4 av = pa[i], bv = pb[i];
            float4 ah, bh;
            ah.x = tf32_rna(av.x); ah.y = tf32_rna(av.y);
            ah.z = tf32_rna(av.z); ah.w = tf32_rna(av.w);
            bh.x = tf32_rna(bv.x); bh.y = tf32_rna(bv.y);
            bh.z = tf32_rna(bv.z); bh.w = tf32_rna(bv.w);
            *(float4*)&Ah[r * GS + c4 * 4] = ah;
            *(float4*)&Bh[r * GS + c4 * 4] = bh;
            if (PASSES == 3) {
                float4 al, bl;
                al.x = tf32_rna(av.x - ah.x); al.y = tf32_rna(av.y - ah.y);
                al.z = tf32_rna(av.z - ah.z); al.w = tf32_rna(av.w - ah.w);
                bl.x = tf32_rna(bv.x - bh.x); bl.y = tf32_rna(bv.y - bh.y);
                bl.z = tf32_rna(bv.z - bh.z); bl.w = tf32_rna(bv.w - bh.w);
                *(float4*)&Al[r * GS + c4 * 4] = al;
                *(float4*)&Bl[r * GS + c4 * 4] = bl;
            }
        }
        __syncthreads();

        // prefetch next chunk (LDGs overlap the MMA work below)
        if (ch + 1 < kchunks) {
            int off = (ch + 1) * 32;
            #pragma unroll
            for (int i = 0; i < 4; i++) {
                pa[i] = *(const float4*)(Ap[i] + off);
                pb[i] = *(const float4*)(Bp[i] + off);
            }
        }

        // MMA over the 32-K chunk
        #pragma unroll
        for (int kc = 0; kc < 32; kc += 8) {
            uint32_t af[4][4], bf[4][2];
            #pragma unroll
            for (int mt = 0; mt < 4; mt++) frag_a(af[mt], Ah, mw + mt * 16, kc, lane);
            #pragma unroll
            for (int nt = 0; nt < 4; nt++) frag_b(bf[nt], Bh, nw + nt * 8, kc, lane);
            #pragma unroll
            for (int mt = 0; mt < 4; mt++)
                #pragma unroll
                for (int nt = 0; nt < 4; nt++)
                    mma8(acc[mt][nt], af[mt], bf[nt]);

            if (PASSES == 3) {
                uint32_t blf[4][2];
                #pragma unroll
                for (int nt = 0; nt < 4; nt++) frag_b(blf[nt], Bl, nw + nt * 8, kc, lane);
                #pragma unroll
                for (int mt = 0; mt < 4; mt++)
                    #pragma unroll
                    for (int nt = 0; nt < 4; nt++)
                        mma8(acc[mt][nt], af[mt], blf[nt]);

                uint32_t alf[4][4];
                #pragma unroll
                for (int mt = 0; mt < 4; mt++) frag_a(alf[mt], Al, mw + mt * 16, kc, lane);
                #pragma unroll
                for (int mt = 0; mt < 4; mt++)
                    #pragma unroll
                    for (int nt = 0; nt < 4; nt++)
                        mma8(acc[mt][nt], alf[mt], bf[nt]);
            }
        }
        __syncthreads();
    }

    // epilogue: bias + activation + store (float2 per fragment row)
    int r = lane >> 2, c2 = (lane & 3) * 2;
    #pragma unroll
    for (int mt = 0; mt < 4; mt++) {
        #pragma unroll
        for (int nt = 0; nt < 4; nt++) {
            int row = m0 + mw + mt * 16 + r;
            int col = n0 + nw + nt * 8 + c2;
            float b0 = bias ? bias[col] : 0.f;
            float b1 = bias ? bias[col + 1] : 0.f;
            float v0 = acc[mt][nt][0] + b0;
            float v1 = acc[mt][nt][1] + b1;
            float v2 = acc[mt][nt][2] + b0;
            float v3 = acc[mt][nt][3] + b1;
            if (ACT == 1) { v0 = gelu_f(v0); v1 = gelu_f(v1); v2 = gelu_f(v2); v3 = gelu_f(v3); }
            float2 lo; lo.x = v0; lo.y = v1;
            float2 hi; hi.x = v2; hi.y = v3;
            *(float2*)&C[(size_t)row * ldc + col] = lo;
            *(float2*)&C[(size_t)(row + 8) * ldc + col] = hi;
        }
    }
}

#define SMEM3 (4 * 128 * GS * 4)
#define SMEM1 (2 * 128 * GS * 4)

// ---------------------------------------------------------------------------
// Top-32 per row — cached per-thread argmax
// ---------------------------------------------------------------------------
__global__ void topk_kernel(const float* __restrict__ scores,
                            int* __restrict__ idxout) {
    __shared__ float sv[DFF];
    __shared__ float swv[8];
    __shared__ int   swi[8];
    __shared__ int   sgi;
    int n = blockIdx.x, tid = threadIdx.x, w = tid >> 5, lane = tid & 31;
    const float4* s4 = (const float4*)(scores + (size_t)n * DFF);
    for (int i = tid; i < DFF / 4; i += 256)
        ((float4*)sv)[i] = s4[i];
    __syncthreads();

    float lmax = -FLT_MAX; int lidx = tid;
    #pragma unroll
    for (int t = 0; t < 16; t++) {
        int j = tid + 256 * t;
        float v = sv[j];
        if (v > lmax) { lmax = v; lidx = j; }
    }
    for (int r = 0; r < TOPK; r++) {
        float b = lmax; int bi = lidx;
        #pragma unroll
        for (int o = 16; o > 0; o >>= 1) {
            float ov = __shfl_down_sync(0xffffffffu, b, o);
            int   oi = __shfl_down_sync(0xffffffffu, bi, o);
            if (ov > b || (ov == b && oi < bi)) { b = ov; bi = oi; }
        }
        if (lane == 0) { swv[w] = b; swi[w] = bi; }
        __syncthreads();
        if (tid == 0) {
            float gb = swv[0]; int gi = swi[0];
            for (int q = 1; q < 8; q++)
                if (swv[q] > gb || (swv[q] == gb && swi[q] < gi)) { gb = swv[q]; gi = swi[q]; }
            idxout[n * TOPK + r] = gi;
            sgi = gi;
            sv[gi] = -FLT_MAX;
        }
        __syncthreads();
        int gi = sgi;
        if ((gi & 255) == tid) {
            lmax = -FLT_MAX; lidx = tid;
            #pragma unroll
            for (int t = 0; t < 16; t++) {
                int j = tid + 256 * t;
                float v = sv[j];
                if (v > lmax) { lmax = v; lidx = j; }
            }
        }
    }
}

// ---------------------------------------------------------------------------
// Fused per-token kernel
// ---------------------------------------------------------------------------
#define SQKV_STRIDE 388
#define WT_STRIDE   132
#define TOKEN_SMEM_FLOATS (16896 + 1024 + 4096 + 4096 + 2112 + 32 + 32 + 32)

__global__ void token_kernel(const float* __restrict__ x,
                             const float* __restrict__ pats,
                             const float* __restrict__ dirs,
                             const float* __restrict__ outw,
                             const float* __restrict__ outb,
                             const float* __restrict__ wp1,
                             const float* __restrict__ wp1b,
                             const float* __restrict__ wp2,
                             const float* __restrict__ wp2b,
                             const int* __restrict__ idx,
                             const float* __restrict__ qkv,
                             float* __restrict__ out) {
    extern __shared__ float smf[];
    float* sW    = smf;
    float* sx    = smf + 16896;
    float* sao   = sx + 1024;
    float* satd  = sao + 4096;
    float* sg1   = satd + 4096;
    float* sbase = sg1 + 2112;
    float* sgate = sbase + 32;
    int*   skid  = (int*)(sgate + 32);
    float* sqkv  = sW;
    float* satt  = sW + 12416;

    int n = blockIdx.x, tid = threadIdx.x, w = tid >> 5, lane = tid & 31;

    if (tid < TOPK) skid[tid] = idx[n * TOPK + tid];
    ((float4*)sx)[tid] = ((const float4*)x)[(size_t)n * 256 + tid];
    __syncthreads();

    {
        const float* qn = qkv + (size_t)n * (TOPK * 3 * DN);
        for (int i = tid; i < TOPK * 3 * DN; i += 256) {
            int r = i / 384, c = i - r * 384;
            sqkv[r * SQKV_STRIDE + c] = qn[i];
        }
    }

    {
        const float4* xs = (const float4*)sx;
        #pragma unroll
        for (int r = 0; r < 4; r++) {
            int kk = w * 4 + r;
            const float4* p = (const float4*)(pats + (size_t)skid[kk] * DMODEL);
            float s = 0.f;
            #pragma unroll
            for (int j = 0; j < 8; j++) {
                int i = lane + 32 * j;
                float4 a = p[i], b = xs[i];
                s += a.x * b.x + a.y * b.y + a.z * b.z + a.w * b.w;
            }
            s = warp_sum(s);
            if (lane == 0) sbase[kk] = gelu_f(s);
        }
    }
    __syncthreads();

    for (int h = 0; h < NHEADS; h++) {
        #pragma unroll
        for (int it = 0; it < 4; it++) {
            int e = tid + 256 * it;
            int qi = e >> 5, ki = e & 31;
            const float4* q4 = (const float4*)(sqkv + qi * SQKV_STRIDE + h * HDIM);
            const float4* k4 = (const float4*)(sqkv + ki * SQKV_STRIDE + DN + h * HDIM);
            float s = 0.f;
            #pragma unroll
            for (int j = 0; j < 4; j++) {
                float4 a = q4[j], b = k4[j];
                s += a.x * b.x + a.y * b.y + a.z * b.z + a.w * b.w;
            }
            satt[e] = s * 0.25f;
        }
        __syncthreads();
        #pragma unroll
        for (int r = 0; r < 4; r++) {
            int qi = w * 4 + r;
            float v = satt[qi * 32 + lane];
            float m = warp_max(v);
            float e2 = __expf(v - m);
            float s = warp_sum(e2);
            satt[qi * 32 + lane] = e2 / s;
        }
        __syncthreads();
        #pragma unroll
        for (int it = 0; it < 2; it++) {
            int e = tid + 256 * it;
            int qi = e >> 4, dc = e & 15;
            float s = 0.f;
            #pragma unroll
            for (int ki = 0; ki < 32; ki++)
                s = fmaf(satt[qi * 32 + ki], sqkv[ki * SQKV_STRIDE + 2 * DN + h * HDIM + dc], s);
            sao[qi * DN + h * HDIM + dc] = s;
        }
        __syncthreads();
    }

    for (int i = tid; i < DN * DN; i += 256) {
        int o = i >> 7, d = i & 127;
        sW[d * WT_STRIDE + o] = outw[i];
    }
    __syncthreads();
    {
        int rb = w, cb = lane;
        float acc[4][4];
        #pragma unroll
        for (int i = 0; i < 4; i++)
            #pragma unroll
            for (int j = 0; j < 4; j++) acc[i][j] = 0.f;
        for (int d = 0; d < DN; d++) {
            float4 wv = *(const float4*)&sW[d * WT_STRIDE + cb * 4];
            float wa[4] = {wv.x, wv.y, wv.z, wv.w};
            #pragma unroll
            for (int i = 0; i < 4; i++) {
                float a = sao[(rb * 4 + i) * DN + d];
                #pragma unroll
                for (int j = 0; j < 4; j++) acc[i][j] = fmaf(a, wa[j], acc[i][j]);
            }
        }
        #pragma unroll
        for (int i = 0; i < 4; i++)
            #pragma unroll
            for (int j = 0; j < 4; j++)
                satd[(rb * 4 + i) * DN + cb * 4 + j] = acc[i][j] + outb[cb * 4 + j];
    }
    __syncthreads();

    for (int i = tid; i < 64 * DN; i += 256) {
        int o = i >> 7, d = i & 127;
        sW[d * WT_STRIDE + o] = wp1[i];
    }
    __syncthreads();
    {
        int rb = tid >> 4, cb = tid & 15;
        float acc[2][4];
        #pragma unroll
        for (int i = 0; i < 2; i++)
            #pragma unroll
            for (int j = 0; j < 4; j++) acc[i][j] = 0.f;
        for (int d = 0; d < DN; d++) {
            float4 wv = *(const float4*)&sW[d * WT_STRIDE + cb * 4];
            float wa[4] = {wv.x, wv.y, wv.z, wv.w};
            #pragma unroll
            for (int i = 0; i < 2; i++) {
                float a = satd[(rb * 2 + i) * DN + d];
                #pragma unroll
                for (int j = 0; j < 4; j++) acc[i][j] = fmaf(a, wa[j], acc[i][j]);
            }
        }
        #pragma unroll
        for (int i = 0; i < 2; i++)
            #pragma unroll
            for (int j = 0; j < 4; j++)
                sg1[(cb * 4 + j) * 33 + rb * 2 + i] = gelu_f(acc[i][j] + wp1b[cb * 4 + j]);
    }
    __syncthreads();

    if (tid < TOPK) {
        float s = 0.f;
        #pragma unroll
        for (int j = 0; j < 64; j++) s = fmaf(sg1[j * 33 + tid], wp2[j], s);
        float sig = 1.0f / (1.0f + __expf(-(s + wp2b[0])));
        sgate[tid] = sbase[tid] * sig;
    }
    __syncthreads();

    {
        float4 acc; acc.x = acc.y = acc.z = acc.w = 0.f;
        #pragma unroll 4
        for (int k = 0; k < TOPK; k++) {
            float g = sgate[k];
            const float4* dr = (const float4*)(dirs + (size_t)skid[k] * DMODEL);
            float4 v = dr[tid];
            acc.x = fmaf(g, v.x, acc.x);
            acc.y = fmaf(g, v.y, acc.y);
            acc.z = fmaf(g, v.z, acc.z);
            acc.w = fmaf(g, v.w, acc.w);
        }
        ((float4*)out)[(size_t)n * 256 + tid] = acc;
    }
}

// ---------------------------------------------------------------------------
// Launch
// ---------------------------------------------------------------------------
extern "C" void kernel_launch(void* const* d_in, const int* in_sizes, int n_in,
                              void* d_out, int out_size) {
    const float* x    = (const float*)d_in[0];
    const float* pats = (const float*)d_in[1];
    const float* vecs = (const float*)d_in[2];
    const float* dirs = (const float*)d_in[3];
    const float* rw1  = (const float*)d_in[4];
    const float* rw2  = (const float*)d_in[5];
    const float* lng  = (const float*)d_in[6];
    const float* lnb  = (const float*)d_in[7];
    const float* inw  = (const float*)d_in[8];
    const float* inb  = (const float*)d_in[9];
    const float* outw = (const float*)d_in[10];
    const float* outb = (const float*)d_in[11];
    const float* wp1  = (const float*)d_in[12];
    const float* wp1b = (const float*)d_in[13];
    const float* wp2  = (const float*)d_in[14];
    const float* wp2b = (const float*)d_in[15];
    float* out = (float*)d_out;

    float *p_xn, *p_h, *p_scores, *p_qkv;
    int *p_idx;
    cudaGetSymbolAddress((void**)&p_xn, g_xn);
    cudaGetSymbolAddress((void**)&p_h, g_h);
    cudaGetSymbolAddress((void**)&p_scores, g_scores);
    cudaGetSymbolAddress((void**)&p_idx, g_idx);
    cudaGetSymbolAddress((void**)&p_qkv, g_qkv);

    static int attr_set = 0;
    if (!attr_set) {
        cudaFuncSetAttribute(token_kernel,
                             cudaFuncAttributeMaxDynamicSharedMemorySize,
                             TOKEN_SMEM_FLOATS * 4);
        cudaFuncSetAttribute(mma_gemm<1, 3>,
                             cudaFuncAttributeMaxDynamicSharedMemorySize, SMEM3);
        cudaFuncSetAttribute(mma_gemm<0, 3>,
                             cudaFuncAttributeMaxDynamicSharedMemorySize, SMEM3);
        cudaFuncSetAttribute(mma_gemm<0, 1>,
                             cudaFuncAttributeMaxDynamicSharedMemorySize, SMEM1);
        attr_set = 1;
    }

    // 1) LayerNorm
    ln_kernel<<<NTOK, 256>>>(x, lng, lnb, p_xn);

    // 2) h = gelu(xn @ rw1^T)   (3xTF32)
    mma_gemm<1, 3><<<dim3(DMODEL / 128, NTOK / 128), 256, SMEM3>>>(
        p_xn, rw1, nullptr, nullptr, p_h, DMODEL, DMODEL, DMODEL / 32);

    // 3) scores = h @ rw2^T     (3xTF32)
    mma_gemm<0, 3><<<dim3(DFF / 128, NTOK / 128), 256, SMEM3>>>(
        p_h, rw2, nullptr, nullptr, p_scores, DMODEL, DFF, DMODEL / 32);

    // 4) top-32 per token
    topk_kernel<<<NTOK, 256>>>(p_scores, p_idx);

    // 5) qkv = gather(neuron_vecs, idx) @ in_proj_w^T + b   (1xTF32, gate-safe)
    mma_gemm<0, 1><<<dim3((3 * DN) / 128, (NTOK * TOPK) / 128), 256, SMEM1>>>(
        vecs, inw, inb, p_idx, p_qkv, DN, 3 * DN, DN / 32);

    // 6) fused per-token attention + gating + output
    token_kernel<<<NTOK, 256, TOKEN_SMEM_FLOATS * 4>>>(
        x, pats, dirs, outw, outb, wp1, wp1b, wp2, wp2b, p_idx, p_qkv, out);
}